// round 15
// baseline (speedup 1.0000x reference)
#include <cuda_runtime.h>
#include <cuda_fp16.h>
#include <cstdint>

#define K1REAL  100
#define HDIM    256
#define TILE_M  64
#define THREADS 256            // 8 warps: mgrp = wid&1 (m32), ngrp = wid>>1 (n64)
#define NCHUNK  39             // k16 chunks: L1 7 (k pad 112), L2 16, L3 16

#define SMEM_TOTAL 32768       // single fp16 act image, 64 x 512B XOR-swizzled

// fragment-linear fp16 weights (40 slots; slot 39 = prefetch-overread pad)
// per chunk 8192B: [slice s(8)][1024B]: q(2)*512 + L*16 + j*4 + (k&1)*2
__device__ __half WCH[(size_t)40 * 4096];

__device__ __forceinline__ uint32_t smem_u32(const void* p) {
    uint32_t a;
    asm("{ .reg .u64 t; cvta.to.shared.u64 t, %1; cvt.u32.u64 %0, t; }" : "=r"(a) : "l"(p));
    return a;
}
__device__ __forceinline__ void ldsm_x4(uint32_t r[4], uint32_t addr) {
    asm volatile("ldmatrix.sync.aligned.m8n8.x4.shared.b16 {%0,%1,%2,%3}, [%4];"
                 : "=r"(r[0]), "=r"(r[1]), "=r"(r[2]), "=r"(r[3]) : "r"(addr));
}
__device__ __forceinline__ void mma_f16(float d[4], const uint32_t a[4],
                                        uint32_t b0, uint32_t b1) {
    asm volatile(
        "mma.sync.aligned.m16n8k16.row.col.f32.f16.f16.f32 "
        "{%0,%1,%2,%3}, {%4,%5,%6,%7}, {%8,%9}, {%0,%1,%2,%3};"
        : "+f"(d[0]), "+f"(d[1]), "+f"(d[2]), "+f"(d[3])
        : "r"(a[0]), "r"(a[1]), "r"(a[2]), "r"(a[3]), "r"(b0), "r"(b1));
}
// packed fp16 tanh (one MUFU op per pair; output is ready-to-store half2)
__device__ __forceinline__ uint32_t tanh_h2(float lo, float hi) {
    __half2 h = __floats2half2_rn(lo, hi);   // x=lo, y=hi
    uint32_t u = *reinterpret_cast<uint32_t*>(&h);
    uint32_t y;
    asm("tanh.approx.f16x2 %0, %1;" : "=r"(y) : "r"(u));
    return y;
}
// act element (m, k): byte offset m*512 + ((k*2) ^ ((m&7)<<4))  (verified R8-R14)
__device__ __forceinline__ uint32_t act_off(int m, int k) {
    return (uint32_t)m * 512u + (((uint32_t)k * 2u) ^ (((uint32_t)m & 7u) << 4));
}

// ---- weight prep: W[k][n] -> fragment-linear fp16 (layout verified R11-R14) ----
__global__ void wsplit_kernel(const float* __restrict__ W1,
                              const float* __restrict__ W2,
                              const float* __restrict__ W3) {
    int n = threadIdx.x;
    int kidx = blockIdx.x;                  // 0..623 padded k (L1 pad 112)
    const float* W; int kk, Kreal, g;
    if (kidx < 112)      { kk = kidx;       W = W1; Kreal = K1REAL; g = kk >> 4; }
    else if (kidx < 368) { kk = kidx - 112; W = W2; Kreal = HDIM;   g = 7  + (kk >> 4); }
    else                 { kk = kidx - 368; W = W3; Kreal = HDIM;   g = 23 + (kk >> 4); }
    float w = (kk < Kreal) ? W[kk * HDIM + n] : 0.0f;
    int kc = kk & 15;
    int s  = n >> 5, nn = n & 31, q = nn >> 4;
    int j  = ((nn >> 3) & 1) * 2 + ((kc >> 3) & 1);
    int L  = (nn & 7) * 4 + ((kc & 7) >> 1);
    size_t base = (size_t)g * 8192 + (size_t)s * 1024
                + (size_t)q * 512 + (size_t)L * 16 + (size_t)j * 4 + (size_t)(kc & 1) * 2;
    *(__half*)((char*)WCH + base) = __float2half(w);
}

// ---- main kernel ----
__global__ void __launch_bounds__(THREADS, 2)
gnn_mma_kernel(const float* __restrict__ ea,
               const float* __restrict__ b1, const float* __restrict__ b2,
               const float* __restrict__ b3,
               const float* __restrict__ W4, const float* __restrict__ b4,
               float* __restrict__ out, int ntot)
{
    extern __shared__ char smem[];
    const uint32_t sbase = smem_u32(smem);
    const int tid = threadIdx.x, lane = tid & 31, wid = tid >> 5;
    const int m0 = (wid & 1) * 32;          // warp's 32 m-rows
    const int n0 = (wid >> 1) * 64;         // warp's 64 n-cols
    const int row0 = blockIdx.x * TILE_M;

    // e-tile: [m][k0..127] fp16, swizzled (k>=100 zero; only k<112 used)
#pragma unroll
    for (int i = 0; i < 32; i++) {
        int idx = tid + i * THREADS;        // 64*128
        int m = idx >> 7, k = idx & 127;
        int row = row0 + m;
        float v = (k < K1REAL && row < ntot) ? ea[(size_t)row * K1REAL + k] : 0.0f;
        *(__half*)(smem + act_off(m, k)) = __float2half(v);
    }
    __syncthreads();

    // A ldsm addressing (loop-invariant)
    const int midx = lane >> 3, l7 = lane & 7;
    const int arow = (midx & 1) * 8 + l7;               // 0..15 within m16 tile
    const uint32_t a_base = (uint32_t)(m0 + arow) * 512u;
    const uint32_t a_sw   = ((uint32_t)arow & 7u) << 4;
    const uint32_t a_k2   = (uint32_t)(midx >> 1) * 16u;

    // per-lane B pointer: warp reads slices 2*ngrp, 2*ngrp+1 of each chunk
    const char* wlane = (const char*)WCH + (size_t)(wid >> 1) * 2048 + (size_t)lane * 16;

    float acc[2][8][4];
#pragma unroll
    for (int mt = 0; mt < 2; mt++)
#pragma unroll
        for (int nt = 0; nt < 8; nt++)
#pragma unroll
            for (int x = 0; x < 4; x++) acc[mt][nt][x] = 0.0f;

    const int r = lane >> 2, cp2 = (lane & 3) * 2;
    int gbase = 0;

    // preload chunk-0 B fragments: 4 x uint4 = bb[16], layout [s][q][j]
    uint4 pf[4];
#pragma unroll
    for (int i = 0; i < 4; i++) pf[i] = __ldg((const uint4*)(wlane + i * 512));

#pragma unroll
    for (int l = 0; l < 3; l++) {
        const int nch = (l == 0) ? 7 : 16;
        for (int ci = 0; ci < nch; ci++) {
            const int g = gbase + ci;
            uint32_t bb[16];
#pragma unroll
            for (int i = 0; i < 4; i++) {
                bb[i * 4 + 0] = pf[i].x; bb[i * 4 + 1] = pf[i].y;
                bb[i * 4 + 2] = pf[i].z; bb[i * 4 + 3] = pf[i].w;
            }
            // prefetch next chunk's B fragments (slot 39 = pad)
            const char* wpn = wlane + (size_t)(g + 1) * 8192;
#pragma unroll
            for (int i = 0; i < 4; i++) pf[i] = __ldg((const uint4*)(wpn + i * 512));

            const uint32_t abase = sbase + a_base + (((uint32_t)ci * 32u + a_k2) ^ a_sw);
            uint32_t a[8];
            ldsm_x4(a,     abase);            // m-tile 0 (rows m0..m0+15)
            ldsm_x4(a + 4, abase + 8192);     // m-tile 1
#pragma unroll
            for (int nt = 0; nt < 8; nt++) {
                // bb index: slice = nt>>2 (x8), q = (nt>>1)&1 (x4), pair = (nt&1)*2
                uint32_t bx = bb[(nt >> 2) * 8 + ((nt >> 1) & 1) * 4 + (nt & 1) * 2];
                uint32_t by = bb[(nt >> 2) * 8 + ((nt >> 1) & 1) * 4 + (nt & 1) * 2 + 1];
                mma_f16(acc[0][nt], a,     bx, by);
                mma_f16(acc[1][nt], a + 4, bx, by);
            }
        }
        gbase += nch;

        __syncthreads();   // all act reads of this layer done

        if (l < 2) {
            const float* bl = (l == 0) ? b1 : b2;
#pragma unroll
            for (int nt = 0; nt < 8; nt++) {
                int n = n0 + nt * 8 + cp2;
                float bn0 = __ldg(bl + n), bn1 = __ldg(bl + n + 1);
#pragma unroll
                for (int mt = 0; mt < 2; mt++)
#pragma unroll
                    for (int dp = 0; dp < 2; dp++) {
                        int m = m0 + mt * 16 + r + dp * 8;
                        uint32_t th = tanh_h2(acc[mt][nt][dp * 2] + bn0,
                                              acc[mt][nt][dp * 2 + 1] + bn1);
                        *(uint32_t*)(smem + act_off(m, n)) = th;
                        acc[mt][nt][dp * 2] = 0.0f; acc[mt][nt][dp * 2 + 1] = 0.0f;
                    }
            }
            __syncthreads();   // act writes visible before next layer's ldsm
        } else {
            // fused layer-3 epilogue + layer 4
            float part[4] = {0.f, 0.f, 0.f, 0.f};   // idx = mt*2+dp
#pragma unroll
            for (int nt = 0; nt < 8; nt++) {
                int n = n0 + nt * 8 + cp2;
                float bn0 = __ldg(b3 + n), bn1 = __ldg(b3 + n + 1);
                float2 w2 = __ldg((const float2*)(W4 + n));
#pragma unroll
                for (int mt = 0; mt < 2; mt++)
#pragma unroll
                    for (int dp = 0; dp < 2; dp++) {
                        uint32_t th = tanh_h2(acc[mt][nt][dp * 2] + bn0,
                                              acc[mt][nt][dp * 2 + 1] + bn1);
                        __half2 h2 = *reinterpret_cast<__half2*>(&th);
                        part[mt * 2 + dp] += __low2float(h2) * w2.x
                                           + __high2float(h2) * w2.y;
                    }
            }
#pragma unroll
            for (int i = 0; i < 4; i++) {
                part[i] += __shfl_xor_sync(0xffffffff, part[i], 1);
                part[i] += __shfl_xor_sync(0xffffffff, part[i], 2);
            }
            float* psm = (float*)smem;   // act area free after barrier above
            if ((lane & 3) == 0) {
#pragma unroll
                for (int mt = 0; mt < 2; mt++)
#pragma unroll
                    for (int dp = 0; dp < 2; dp++)
                        psm[wid * 32 + mt * 16 + r + dp * 8] = part[mt * 2 + dp];
            }
            __syncthreads();
            if (tid < TILE_M) {
                int mg = tid >> 5, ml = tid & 31;
                float s = 0.0f;
#pragma unroll
                for (int k = 0; k < 4; k++) s += psm[(mg + 2 * k) * 32 + ml];
                float z = s + __ldg(b4);
                int row = row0 + tid;
                if (row < ntot) out[row] = 1.0f / (1.0f + expf(-z));
            }
        }
    }
}

extern "C" void kernel_launch(void* const* d_in, const int* in_sizes, int n_in,
                              void* d_out, int out_size)
{
    // Inputs: x, edge_index, edge_attr, W1, b1, W2, b2, W3, b3, W4, b4
    const float* ea = (const float*)d_in[2];
    const float* W1 = (const float*)d_in[3];
    const float* b1 = (const float*)d_in[4];
    const float* W2 = (const float*)d_in[5];
    const float* b2 = (const float*)d_in[6];
    const float* W3 = (const float*)d_in[7];
    const float* b3 = (const float*)d_in[8];
    const float* W4 = (const float*)d_in[9];
    const float* b4 = (const float*)d_in[10];
    float* out = (float*)d_out;

    int ntot = out_size;                              // 500000
    int grid = (ntot + TILE_M - 1) / TILE_M;          // 7813

    wsplit_kernel<<<624, 256>>>(W1, W2, W3);

    cudaFuncSetAttribute(gnn_mma_kernel,
                         cudaFuncAttributeMaxDynamicSharedMemorySize, SMEM_TOTAL);
    gnn_mma_kernel<<<grid, THREADS, SMEM_TOTAL>>>(ea, b1, b2, b3, W4, b4, out, ntot);
}

// round 16
// speedup vs baseline: 1.0420x; 1.0420x over previous
#include <cuda_runtime.h>
#include <cuda_fp16.h>
#include <cstdint>

#define K1REAL  100
#define HDIM    256
#define TILE_M  64
#define THREADS 256            // 8 warps; warp w owns m0..63 x n[w*32, w*32+32)
#define NCHUNK  39             // k16 chunks: L1 7 (k pad 112), L2 16, L3 16

#define SMEM_TOTAL 32768       // single fp16 act image, 64 x 512B XOR-swizzled

// fragment-linear fp16 weights (40 slots; slot 39 = prefetch-overread pad)
__device__ __half WCH[(size_t)40 * 4096];

__device__ __forceinline__ uint32_t smem_u32(const void* p) {
    uint32_t a;
    asm("{ .reg .u64 t; cvta.to.shared.u64 t, %1; cvt.u32.u64 %0, t; }" : "=r"(a) : "l"(p));
    return a;
}
__device__ __forceinline__ void ldsm_x4(uint32_t r[4], uint32_t addr) {
    asm volatile("ldmatrix.sync.aligned.m8n8.x4.shared.b16 {%0,%1,%2,%3}, [%4];"
                 : "=r"(r[0]), "=r"(r[1]), "=r"(r[2]), "=r"(r[3]) : "r"(addr));
}
__device__ __forceinline__ void mma_f16(float d[4], const uint32_t a[4],
                                        uint32_t b0, uint32_t b1) {
    asm volatile(
        "mma.sync.aligned.m16n8k16.row.col.f32.f16.f16.f32 "
        "{%0,%1,%2,%3}, {%4,%5,%6,%7}, {%8,%9}, {%0,%1,%2,%3};"
        : "+f"(d[0]), "+f"(d[1]), "+f"(d[2]), "+f"(d[3])
        : "r"(a[0]), "r"(a[1]), "r"(a[2]), "r"(a[3]), "r"(b0), "r"(b1));
}
// packed fp16 tanh (one MUFU per pair; output ready-to-store; validated R15)
__device__ __forceinline__ uint32_t tanh_h2(float lo, float hi) {
    __half2 h = __floats2half2_rn(lo, hi);
    uint32_t u = *reinterpret_cast<uint32_t*>(&h);
    uint32_t y;
    asm("tanh.approx.f16x2 %0, %1;" : "=r"(y) : "r"(u));
    return y;
}
// act element (m, k): byte offset m*512 + ((k*2) ^ ((m&7)<<4))  (verified R8-R15)
__device__ __forceinline__ uint32_t act_off(int m, int k) {
    return (uint32_t)m * 512u + (((uint32_t)k * 2u) ^ (((uint32_t)m & 7u) << 4));
}

// ---- weight prep: W[k][n] -> fragment-linear fp16 (layout verified R11-R15) ----
__global__ void wsplit_kernel(const float* __restrict__ W1,
                              const float* __restrict__ W2,
                              const float* __restrict__ W3) {
    int n = threadIdx.x;
    int kidx = blockIdx.x;                  // 0..623 padded k (L1 pad 112)
    const float* W; int kk, Kreal, g;
    if (kidx < 112)      { kk = kidx;       W = W1; Kreal = K1REAL; g = kk >> 4; }
    else if (kidx < 368) { kk = kidx - 112; W = W2; Kreal = HDIM;   g = 7  + (kk >> 4); }
    else                 { kk = kidx - 368; W = W3; Kreal = HDIM;   g = 23 + (kk >> 4); }
    float w = (kk < Kreal) ? W[kk * HDIM + n] : 0.0f;
    int kc = kk & 15;
    int s  = n >> 5, nn = n & 31, q = nn >> 4;
    int j  = ((nn >> 3) & 1) * 2 + ((kc >> 3) & 1);
    int L  = (nn & 7) * 4 + ((kc & 7) >> 1);
    size_t base = (size_t)g * 8192 + (size_t)s * 1024
                + (size_t)q * 512 + (size_t)L * 16 + (size_t)j * 4 + (size_t)(kc & 1) * 2;
    *(__half*)((char*)WCH + base) = __float2half(w);
}

// ---- main kernel ----
__global__ void __launch_bounds__(THREADS, 2)
gnn_mma_kernel(const float* __restrict__ ea,
               const float* __restrict__ b1, const float* __restrict__ b2,
               const float* __restrict__ b3,
               const float* __restrict__ W4, const float* __restrict__ b4,
               float* __restrict__ out, int ntot)
{
    extern __shared__ char smem[];
    const uint32_t sbase = smem_u32(smem);
    const int tid = threadIdx.x, lane = tid & 31, wid = tid >> 5;
    const int row0 = blockIdx.x * TILE_M;

    // e-tile: [m][k0..127] fp16, swizzled (k>=100 zero; only k<112 used)
#pragma unroll
    for (int i = 0; i < 32; i++) {
        int idx = tid + i * THREADS;        // 64*128
        int m = idx >> 7, k = idx & 127;
        int row = row0 + m;
        float v = (k < K1REAL && row < ntot) ? ea[(size_t)row * K1REAL + k] : 0.0f;
        *(__half*)(smem + act_off(m, k)) = __float2half(v);
    }
    __syncthreads();

    // A ldsm addressing (loop-invariant)
    const int midx = lane >> 3, l7 = lane & 7;
    const int arow = (midx & 1) * 8 + l7;               // 0..15
    const uint32_t a_base = (uint32_t)arow * 512u;
    const uint32_t a_sw   = ((uint32_t)arow & 7u) << 4;
    const uint32_t a_k2   = (uint32_t)(midx >> 1) * 16u;

    const char* wlane = (const char*)WCH + (size_t)wid * 1024 + (size_t)lane * 16;

    float acc[4][4][4];
#pragma unroll
    for (int mt = 0; mt < 4; mt++)
#pragma unroll
        for (int nt = 0; nt < 4; nt++)
#pragma unroll
            for (int x = 0; x < 4; x++) acc[mt][nt][x] = 0.0f;

    const int r = lane >> 2, cp2 = (lane & 3) * 2;
    int gbase = 0;

    // preload chunk-0 B fragments
    uint32_t bh[8];
    {
        uint4 t0 = __ldg((const uint4*)wlane);
        uint4 t1 = __ldg((const uint4*)(wlane + 512));
        bh[0]=t0.x; bh[1]=t0.y; bh[2]=t0.z; bh[3]=t0.w;
        bh[4]=t1.x; bh[5]=t1.y; bh[6]=t1.z; bh[7]=t1.w;
    }

#pragma unroll
    for (int l = 0; l < 3; l++) {
        const int nch = (l == 0) ? 7 : 16;
        for (int ci = 0; ci < nch; ci++) {
            const int g = gbase + ci;
            // prefetch next chunk's B fragments (slot 39 = pad)
            const char* wpn = wlane + (size_t)(g + 1) * 8192;
            uint4 p0 = __ldg((const uint4*)wpn);
            uint4 p1 = __ldg((const uint4*)(wpn + 512));

            const uint32_t abase = sbase + a_base + (((uint32_t)ci * 32u + a_k2) ^ a_sw);
            uint32_t a[16];
#pragma unroll
            for (int mt = 0; mt < 4; mt++) ldsm_x4(a + mt * 4, abase + mt * 8192);
#pragma unroll
            for (int nt = 0; nt < 4; nt++) {
                uint32_t bx = bh[(nt >> 1) * 4 + (nt & 1) * 2];
                uint32_t by = bh[(nt >> 1) * 4 + (nt & 1) * 2 + 1];
#pragma unroll
                for (int mt = 0; mt < 4; mt++) mma_f16(acc[mt][nt], a + mt * 4, bx, by);
            }
            bh[0]=p0.x; bh[1]=p0.y; bh[2]=p0.z; bh[3]=p0.w;
            bh[4]=p1.x; bh[5]=p1.y; bh[6]=p1.z; bh[7]=p1.w;
        }
        gbase += nch;

        __syncthreads();   // all act reads of this layer done

        if (l < 2) {
            const float* bl = (l == 0) ? b1 : b2;
#pragma unroll
            for (int nt = 0; nt < 4; nt++) {
                int n = wid * 32 + nt * 8 + cp2;
                float bn0 = __ldg(bl + n), bn1 = __ldg(bl + n + 1);
#pragma unroll
                for (int mt = 0; mt < 4; mt++)
#pragma unroll
                    for (int dp = 0; dp < 2; dp++) {
                        int m = mt * 16 + r + dp * 8;
                        uint32_t th = tanh_h2(acc[mt][nt][dp * 2] + bn0,
                                              acc[mt][nt][dp * 2 + 1] + bn1);
                        *(uint32_t*)(smem + act_off(m, n)) = th;
                        acc[mt][nt][dp * 2] = 0.0f; acc[mt][nt][dp * 2 + 1] = 0.0f;
                    }
            }
            __syncthreads();   // act writes visible before next layer's ldsm
        } else {
            // fused layer-3 epilogue + layer 4
            float part[8];     // idx = mt*2 + dp, m = mt*16 + r + dp*8
#pragma unroll
            for (int i = 0; i < 8; i++) part[i] = 0.0f;
#pragma unroll
            for (int nt = 0; nt < 4; nt++) {
                int n = wid * 32 + nt * 8 + cp2;
                float bn0 = __ldg(b3 + n), bn1 = __ldg(b3 + n + 1);
                float2 w2 = __ldg((const float2*)(W4 + n));
#pragma unroll
                for (int mt = 0; mt < 4; mt++)
#pragma unroll
                    for (int dp = 0; dp < 2; dp++) {
                        uint32_t th = tanh_h2(acc[mt][nt][dp * 2] + bn0,
                                              acc[mt][nt][dp * 2 + 1] + bn1);
                        __half2 h2 = *reinterpret_cast<__half2*>(&th);
                        part[mt * 2 + dp] += __low2float(h2) * w2.x
                                           + __high2float(h2) * w2.y;
                    }
            }
#pragma unroll
            for (int i = 0; i < 8; i++) {
                part[i] += __shfl_xor_sync(0xffffffff, part[i], 1);
                part[i] += __shfl_xor_sync(0xffffffff, part[i], 2);
            }
            float* psm = (float*)smem;   // act area free after barrier above
            if ((lane & 3) == 0) {
#pragma unroll
                for (int mt = 0; mt < 4; mt++)
#pragma unroll
                    for (int dp = 0; dp < 2; dp++)
                        psm[wid * 64 + mt * 16 + r + dp * 8] = part[mt * 2 + dp];
            }
            __syncthreads();
            if (tid < TILE_M) {
                float s = 0.0f;
#pragma unroll
                for (int w = 0; w < 8; w++) s += psm[w * 64 + tid];
                float z = s + __ldg(b4);
                int row = row0 + tid;
                if (row < ntot) out[row] = 1.0f / (1.0f + expf(-z));
            }
        }
    }
}

extern "C" void kernel_launch(void* const* d_in, const int* in_sizes, int n_in,
                              void* d_out, int out_size)
{
    // Inputs: x, edge_index, edge_attr, W1, b1, W2, b2, W3, b3, W4, b4
    const float* ea = (const float*)d_in[2];
    const float* W1 = (const float*)d_in[3];
    const float* b1 = (const float*)d_in[4];
    const float* W2 = (const float*)d_in[5];
    const float* b2 = (const float*)d_in[6];
    const float* W3 = (const float*)d_in[7];
    const float* b3 = (const float*)d_in[8];
    const float* W4 = (const float*)d_in[9];
    const float* b4 = (const float*)d_in[10];
    float* out = (float*)d_out;

    int ntot = out_size;                              // 500000
    int grid = (ntot + TILE_M - 1) / TILE_M;          // 7813

    wsplit_kernel<<<624, 256>>>(W1, W2, W3);

    cudaFuncSetAttribute(gnn_mma_kernel,
                         cudaFuncAttributeMaxDynamicSharedMemorySize, SMEM_TOTAL);
    gnn_mma_kernel<<<grid, THREADS, SMEM_TOTAL>>>(ea, b1, b2, b3, W4, b4, out, ntot);
}

// round 17
// speedup vs baseline: 1.1263x; 1.0809x over previous
#include <cuda_runtime.h>
#include <cuda_fp16.h>
#include <cstdint>

#define K1REAL  100
#define HDIM    256
#define TILE_M  64
#define THREADS 256            // 8 warps; warp w owns m0..63 x n[w*32, w*32+32)
#define NCHUNK  39             // k16 chunks: L1 7 (k pad 112), L2 16, L3 16

#define SM_A0   0              // act ping buffer (64 x 512B, XOR-swizzled)
#define SM_A1   32768          // act pong buffer
#define SMEM_TOTAL 65536       // 2 CTAs/SM (reg-limited anyway)

// fragment-linear fp16 weights (40 slots; slot 39 = prefetch-overread pad)
__device__ __half WCH[(size_t)40 * 4096];

__device__ __forceinline__ uint32_t smem_u32(const void* p) {
    uint32_t a;
    asm("{ .reg .u64 t; cvta.to.shared.u64 t, %1; cvt.u32.u64 %0, t; }" : "=r"(a) : "l"(p));
    return a;
}
__device__ __forceinline__ void ldsm_x4(uint32_t r[4], uint32_t addr) {
    asm volatile("ldmatrix.sync.aligned.m8n8.x4.shared.b16 {%0,%1,%2,%3}, [%4];"
                 : "=r"(r[0]), "=r"(r[1]), "=r"(r[2]), "=r"(r[3]) : "r"(addr));
}
__device__ __forceinline__ void mma_f16(float d[4], const uint32_t a[4],
                                        uint32_t b0, uint32_t b1) {
    asm volatile(
        "mma.sync.aligned.m16n8k16.row.col.f32.f16.f16.f32 "
        "{%0,%1,%2,%3}, {%4,%5,%6,%7}, {%8,%9}, {%0,%1,%2,%3};"
        : "+f"(d[0]), "+f"(d[1]), "+f"(d[2]), "+f"(d[3])
        : "r"(a[0]), "r"(a[1]), "r"(a[2]), "r"(a[3]), "r"(b0), "r"(b1));
}
__device__ __forceinline__ float tanh_fast(float x) {
    float y; asm("tanh.approx.f32 %0, %1;" : "=f"(y) : "f"(x)); return y;
}
__device__ __forceinline__ uint32_t pack_h2(float a, float b) {
    __half2 t = __floats2half2_rn(a, b);
    return *reinterpret_cast<uint32_t*>(&t);
}
// act element (m, k): byte offset m*512 + ((k*2) ^ ((m&7)<<4))  (verified R8-R16)
__device__ __forceinline__ uint32_t act_off(int m, int k) {
    return (uint32_t)m * 512u + (((uint32_t)k * 2u) ^ (((uint32_t)m & 7u) << 4));
}

// ---- weight prep: W[k][n] -> fragment-linear fp16 (layout verified R11-R16) ----
__global__ void wsplit_kernel(const float* __restrict__ W1,
                              const float* __restrict__ W2,
                              const float* __restrict__ W3) {
    int n = threadIdx.x;
    int kidx = blockIdx.x;                  // 0..623 padded k (L1 pad 112)
    const float* W; int kk, Kreal, g;
    if (kidx < 112)      { kk = kidx;       W = W1; Kreal = K1REAL; g = kk >> 4; }
    else if (kidx < 368) { kk = kidx - 112; W = W2; Kreal = HDIM;   g = 7  + (kk >> 4); }
    else                 { kk = kidx - 368; W = W3; Kreal = HDIM;   g = 23 + (kk >> 4); }
    float w = (kk < Kreal) ? W[kk * HDIM + n] : 0.0f;
    int kc = kk & 15;
    int s  = n >> 5, nn = n & 31, q = nn >> 4;
    int j  = ((nn >> 3) & 1) * 2 + ((kc >> 3) & 1);
    int L  = (nn & 7) * 4 + ((kc & 7) >> 1);
    size_t base = (size_t)g * 8192 + (size_t)s * 1024
                + (size_t)q * 512 + (size_t)L * 16 + (size_t)j * 4 + (size_t)(kc & 1) * 2;
    *(__half*)((char*)WCH + base) = __float2half(w);
}

// ---- main kernel ----
__global__ void __launch_bounds__(THREADS, 2)
gnn_mma_kernel(const float* __restrict__ ea,
               const float* __restrict__ b1, const float* __restrict__ b2,
               const float* __restrict__ b3,
               const float* __restrict__ W4, const float* __restrict__ b4,
               float* __restrict__ out, int ntot)
{
    extern __shared__ char smem[];
    const uint32_t sbase = smem_u32(smem);
    const int tid = threadIdx.x, lane = tid & 31, wid = tid >> 5;
    const int row0 = blockIdx.x * TILE_M;

    uint32_t rd = SM_A0, wr = SM_A1;

    // e-tile via float4: 64 rows x 25 float4 = 1600 loads (k<100)
#pragma unroll
    for (int i = 0; i < 7; i++) {
        int idx = tid + i * THREADS;
        if (idx < TILE_M * 25) {
            int m = idx / 25, q = idx - m * 25;
            int row = row0 + m;
            float4 v = make_float4(0.f, 0.f, 0.f, 0.f);
            if (row < ntot) v = __ldg((const float4*)(ea + (size_t)row * K1REAL + 4 * q));
            uint32_t h01 = pack_h2(v.x, v.y);
            uint32_t h23 = pack_h2(v.z, v.w);
            unsigned long long both = (unsigned long long)h01
                                    | ((unsigned long long)h23 << 32);
            uint32_t off = act_off(m, 4 * q);          // 8B-aligned (sw is 16x)
            asm volatile("st.shared.u64 [%0], %1;"
                         :: "r"(sbase + rd + off), "l"(both));
        }
    }
    // zero-pad k in [100,112): 64 rows x 6 half2
    if (tid < TILE_M * 6) {
        int m = tid / 6, j = tid - m * 6;
        uint32_t off = act_off(m, 100 + 2 * j);
        asm volatile("st.shared.u32 [%0], %1;" :: "r"(sbase + rd + off), "r"(0u));
    }
    __syncthreads();

    // A ldsm addressing (loop-invariant)
    const int midx = lane >> 3, l7 = lane & 7;
    const int arow = (midx & 1) * 8 + l7;               // 0..15
    const uint32_t a_base = (uint32_t)arow * 512u;
    const uint32_t a_sw   = ((uint32_t)arow & 7u) << 4;
    const uint32_t a_k2   = (uint32_t)(midx >> 1) * 16u;

    const char* wlane = (const char*)WCH + (size_t)wid * 1024 + (size_t)lane * 16;

    float acc[4][4][4];
#pragma unroll
    for (int mt = 0; mt < 4; mt++)
#pragma unroll
        for (int nt = 0; nt < 4; nt++)
#pragma unroll
            for (int x = 0; x < 4; x++) acc[mt][nt][x] = 0.0f;

    const int r = lane >> 2, cp2 = (lane & 3) * 2;
    int gbase = 0;

    // preload chunk-0 B fragments
    uint32_t bh[8];
    {
        uint4 t0 = __ldg((const uint4*)wlane);
        uint4 t1 = __ldg((const uint4*)(wlane + 512));
        bh[0]=t0.x; bh[1]=t0.y; bh[2]=t0.z; bh[3]=t0.w;
        bh[4]=t1.x; bh[5]=t1.y; bh[6]=t1.z; bh[7]=t1.w;
    }

#pragma unroll
    for (int l = 0; l < 3; l++) {
        const int nch = (l == 0) ? 7 : 16;
        for (int ci = 0; ci < nch; ci++) {
            const int g = gbase + ci;
            // prefetch next chunk's B fragments (slot 39 = pad)
            const char* wpn = wlane + (size_t)(g + 1) * 8192;
            uint4 p0 = __ldg((const uint4*)wpn);
            uint4 p1 = __ldg((const uint4*)(wpn + 512));

            const uint32_t abase = sbase + rd + a_base
                                 + (((uint32_t)ci * 32u + a_k2) ^ a_sw);
            uint32_t a[16];
#pragma unroll
            for (int mt = 0; mt < 4; mt++) ldsm_x4(a + mt * 4, abase + mt * 8192);
#pragma unroll
            for (int nt = 0; nt < 4; nt++) {
                uint32_t bx = bh[(nt >> 1) * 4 + (nt & 1) * 2];
                uint32_t by = bh[(nt >> 1) * 4 + (nt & 1) * 2 + 1];
#pragma unroll
                for (int mt = 0; mt < 4; mt++) mma_f16(acc[mt][nt], a + mt * 4, bx, by);
            }
            bh[0]=p0.x; bh[1]=p0.y; bh[2]=p0.z; bh[3]=p0.w;
            bh[4]=p1.x; bh[5]=p1.y; bh[6]=p1.z; bh[7]=p1.w;
        }
        gbase += nch;

        if (l < 2) {
            // epilogue writes PONG buffer -> no pre-barrier needed
            const float* bl = (l == 0) ? b1 : b2;
#pragma unroll
            for (int nt = 0; nt < 4; nt++) {
                int n = wid * 32 + nt * 8 + cp2;
                float bn0 = __ldg(bl + n), bn1 = __ldg(bl + n + 1);
#pragma unroll
                for (int mt = 0; mt < 4; mt++)
#pragma unroll
                    for (int dp = 0; dp < 2; dp++) {
                        int m = mt * 16 + r + dp * 8;
                        float t0 = tanh_fast(acc[mt][nt][dp * 2]     + bn0);
                        float t1 = tanh_fast(acc[mt][nt][dp * 2 + 1] + bn1);
                        *(uint32_t*)(smem + wr + act_off(m, n)) = pack_h2(t0, t1);
                        acc[mt][nt][dp * 2] = 0.0f; acc[mt][nt][dp * 2 + 1] = 0.0f;
                    }
            }
            __syncthreads();   // pong writes visible before next layer's ldsm
            uint32_t t = rd; rd = wr; wr = t;
        } else {
            // fused layer-3 epilogue + layer 4 (partials into PONG buffer)
            float part[8];     // idx = mt*2 + dp, m = mt*16 + r + dp*8
#pragma unroll
            for (int i = 0; i < 8; i++) part[i] = 0.0f;
#pragma unroll
            for (int nt = 0; nt < 4; nt++) {
                int n = wid * 32 + nt * 8 + cp2;
                float bn0 = __ldg(b3 + n), bn1 = __ldg(b3 + n + 1);
                float2 w2 = __ldg((const float2*)(W4 + n));
#pragma unroll
                for (int mt = 0; mt < 4; mt++)
#pragma unroll
                    for (int dp = 0; dp < 2; dp++) {
                        float t0 = tanh_fast(acc[mt][nt][dp * 2]     + bn0);
                        float t1 = tanh_fast(acc[mt][nt][dp * 2 + 1] + bn1);
                        part[mt * 2 + dp] += t0 * w2.x + t1 * w2.y;
                    }
            }
#pragma unroll
            for (int i = 0; i < 8; i++) {
                part[i] += __shfl_xor_sync(0xffffffff, part[i], 1);
                part[i] += __shfl_xor_sync(0xffffffff, part[i], 2);
            }
            float* psm = (float*)(smem + wr);   // pong buffer, no read conflicts
            if ((lane & 3) == 0) {
#pragma unroll
                for (int mt = 0; mt < 4; mt++)
#pragma unroll
                    for (int dp = 0; dp < 2; dp++)
                        psm[wid * 64 + mt * 16 + r + dp * 8] = part[mt * 2 + dp];
            }
            __syncthreads();
            if (tid < TILE_M) {
                float s = 0.0f;
#pragma unroll
                for (int w = 0; w < 8; w++) s += psm[w * 64 + tid];
                float z = s + __ldg(b4);
                int row = row0 + tid;
                if (row < ntot) out[row] = 1.0f / (1.0f + expf(-z));
            }
        }
    }
}

extern "C" void kernel_launch(void* const* d_in, const int* in_sizes, int n_in,
                              void* d_out, int out_size)
{
    // Inputs: x, edge_index, edge_attr, W1, b1, W2, b2, W3, b3, W4, b4
    const float* ea = (const float*)d_in[2];
    const float* W1 = (const float*)d_in[3];
    const float* b1 = (const float*)d_in[4];
    const float* W2 = (const float*)d_in[5];
    const float* b2 = (const float*)d_in[6];
    const float* W3 = (const float*)d_in[7];
    const float* b3 = (const float*)d_in[8];
    const float* W4 = (const float*)d_in[9];
    const float* b4 = (const float*)d_in[10];
    float* out = (float*)d_out;

    int ntot = out_size;                              // 500000
    int grid = (ntot + TILE_M - 1) / TILE_M;          // 7813

    wsplit_kernel<<<624, 256>>>(W1, W2, W3);

    cudaFuncSetAttribute(gnn_mma_kernel,
                         cudaFuncAttributeMaxDynamicSharedMemorySize, SMEM_TOTAL);
    gnn_mma_kernel<<<grid, THREADS, SMEM_TOTAL>>>(ea, b1, b2, b3, W4, b4, out, ntot);
}